// round 7
// baseline (speedup 1.0000x reference)
#include <cuda_runtime.h>
#include <cuda_fp16.h>
#include <cstdint>

// DRR renderer: line integrals of trilinearly-interpolated 256^3 volume.
//
// R6: software-pipelined inner loop (prefetch sample i+1's 8 loads while
// consuming sample i) + magic-number floor (fadd_rd) to shorten chains.
// Volume is transposed to x-fastest fp16 (32MB, L2-resident).

#define DV 256
#define DV2 (DV * DV)

__device__ __half g_volT[DV * DV * DV];  // 32 MB, x-fastest layout

__device__ __forceinline__ __half2 u32_as_half2(uint32_t x) {
    __half2 h;
    *reinterpret_cast<uint32_t*>(&h) = x;
    return h;
}

// -------- transpose: g_volT[k*DV2 + j*DV + i] = (half)vol[i*DV2 + j*DV + k] --------
__global__ void __launch_bounds__(256) transpose_vol(const float* __restrict__ v) {
    __shared__ float tile[32][65];            // [k_local][i_local(64)+pad]
    const int j  = blockIdx.z;
    const int i0 = blockIdx.y * 64;
    const int k0 = blockIdx.x * 32;
    const int tx = threadIdx.x, ty = threadIdx.y;

#pragma unroll
    for (int n = 0; n < 8; n++) {
        const int il = ty + n * 8;
        tile[tx][il] = v[(size_t)(i0 + il) * DV2 + j * DV + (k0 + tx)];
    }
    __syncthreads();
#pragma unroll
    for (int n = 0; n < 4; n++) {
        const int kl = ty + n * 8;
        const __half2 h = __floats2half2_rn(tile[kl][2 * tx], tile[kl][2 * tx + 1]);
        ((__half2*)g_volT)[(((size_t)(k0 + kl) * DV2 + j * DV + i0) >> 1) + tx] = h;
    }
}

// ------------------------- per-sample helpers -------------------------------

struct Samp {
    uint32_t a[8];      // raw u32 (half2-pair) loads
    float wx, wy, wz;
    uint32_t sel;
};

// issue the address math + 8 loads for sample at parameter t
__device__ __forceinline__ void prefetch_samp(
    float t, float dx, float dy, float dz,
    float p0x, float p0y, float p0z,
    const uint32_t* __restrict__ h2, Samp& S)
{
    const float CMAX = 254.99998f;
    const float MAGIC = 8388608.0f;  // 2^23

    const float ix = fmaf(t, dx, p0x);
    const float iy = fmaf(t, dy, p0y);
    const float iz = fmaf(t, dz, p0z);

    const float cx = fminf(fmaxf(ix, 0.0f), CMAX);
    const float cy = fminf(fmaxf(iy, 0.0f), CMAX);
    const float cz = fminf(fmaxf(iz, 0.0f), CMAX);

    // round-down magic: mantissa low bits hold floor(c) for c in [0,255)
    const float mx = __fadd_rd(cx, MAGIC);
    const float my = __fadd_rd(cy, MAGIC);
    const float mz = __fadd_rd(cz, MAGIC);
    const uint32_t bi = __float_as_uint(mx) & 0xFFu;
    const uint32_t bj = __float_as_uint(my) & 0xFFu;
    const uint32_t bk = __float_as_uint(mz) & 0xFFu;

    S.wx = cx - (mx - MAGIC);
    S.wy = cy - (my - MAGIC);
    S.wz = cz - (mz - MAGIC);

    const int e = (int)(((bk << 16) | (bj << 8) | bi) >> 1);
    S.sel = (bi & 1u) ? 0x5432u : 0x3210u;

    S.a[0] = __ldg(h2 + e);
    S.a[1] = __ldg(h2 + e + 1);
    S.a[2] = __ldg(h2 + e + 128);
    S.a[3] = __ldg(h2 + e + 129);
    S.a[4] = __ldg(h2 + e + 32768);
    S.a[5] = __ldg(h2 + e + 32769);
    S.a[6] = __ldg(h2 + e + 32896);
    S.a[7] = __ldg(h2 + e + 32897);
}

__device__ __forceinline__ float consume_samp(const Samp& S)
{
    const __half2 p0h = u32_as_half2(__byte_perm(S.a[0], S.a[1], S.sel));
    const __half2 p1h = u32_as_half2(__byte_perm(S.a[2], S.a[3], S.sel));
    const __half2 p2h = u32_as_half2(__byte_perm(S.a[4], S.a[5], S.sel));
    const __half2 p3h = u32_as_half2(__byte_perm(S.a[6], S.a[7], S.sel));

    const float v000 = __low2float(p0h), v100 = __high2float(p0h);
    const float v010 = __low2float(p1h), v110 = __high2float(p1h);
    const float v001 = __low2float(p2h), v101 = __high2float(p2h);
    const float v011 = __low2float(p3h), v111 = __high2float(p3h);

    const float c00 = fmaf(S.wx, v100 - v000, v000);
    const float c01 = fmaf(S.wx, v110 - v010, v010);
    const float c10 = fmaf(S.wx, v101 - v001, v001);
    const float c11 = fmaf(S.wx, v111 - v011, v011);
    const float c0  = fmaf(S.wy, c01 - c00, c00);
    const float c1  = fmaf(S.wy, c11 - c10, c10);
    return fmaf(S.wz, c1 - c0, c0);
}

// ----------------------------- main ray kernel ------------------------------
// 2 threads per ray: sub-thread handles samples s0+sub, s0+sub+2, ...
__global__ void __launch_bounds__(256) drr_kernel(
    const float* __restrict__ src,
    const float* __restrict__ tgt,
    const float* __restrict__ spacing,
    const float* __restrict__ origin,
    const int*   __restrict__ nptr,
    float* __restrict__ out,
    int n_rays)
{
    const int tid = blockIdx.x * blockDim.x + threadIdx.x;
    const int r   = tid >> 1;
    const int sub = tid & 1;
    if (r >= n_rays) return;

    const int n = nptr ? __ldg(nptr) : 128;

    const float ox = __ldg(origin + 0), oy = __ldg(origin + 1), oz = __ldg(origin + 2);
    const float hx = __ldg(spacing + 0), hy = __ldg(spacing + 1), hz = __ldg(spacing + 2);

    const float sxm = __ldg(src + 3 * r + 0);
    const float sym = __ldg(src + 3 * r + 1);
    const float szm = __ldg(src + 3 * r + 2);
    const float txm = __ldg(tgt + 3 * r + 0);
    const float tym = __ldg(tgt + 3 * r + 1);
    const float tzm = __ldg(tgt + 3 * r + 2);

    const float rx = txm - sxm, ry = tym - sym, rz = tzm - szm;
    const float raylen = sqrtf(fmaf(rx, rx, fmaf(ry, ry, rz * rz)));

    // voxel-space parametrization: idx(t) = p0 + t * d,  t = s/(n-1)
    const float p0x = (sxm - ox) / hx, p0y = (sym - oy) / hy, p0z = (szm - oz) / hz;
    const float dx = rx / hx, dy = ry / hy, dz = rz / hz;

    const float DM1 = (float)(DV - 1);

    // slab clip in t
    float tlo = 0.0f, thi = 1.0f;
    bool empty = false;
    {
        float p0[3] = {p0x, p0y, p0z};
        float dd[3] = {dx, dy, dz};
#pragma unroll
        for (int a = 0; a < 3; a++) {
            if (fabsf(dd[a]) > 1e-8f) {
                float inv = 1.0f / dd[a];
                float t1 = (0.0f - p0[a]) * inv;
                float t2 = (DM1 - p0[a]) * inv;
                tlo = fmaxf(tlo, fminf(t1, t2));
                thi = fminf(thi, fmaxf(t1, t2));
            } else if (p0[a] < 0.0f || p0[a] > DM1) {
                empty = true;
            }
        }
    }

    float acc = 0.0f;
    const float nm1 = (float)(n - 1);
    const float invn = (n > 1) ? 1.0f / nm1 : 0.0f;

    if (!empty && thi >= tlo) {
        // samples strictly within [tlo,thi] -> inside by construction
        const int s0 = max(0, (int)ceilf(fmaf(tlo, nm1, -1e-3f)));
        const int s1 = min(n - 1, (int)floorf(fmaf(thi, nm1, 1e-3f)));
        const int sfirst = s0 + sub;

        if (s1 >= sfirst) {
            const int cnt = ((s1 - sfirst) >> 1) + 1;
            const uint32_t* __restrict__ h2 = (const uint32_t*)g_volT;

            const float t0    = (float)sfirst * invn;
            const float tstep = 2.0f * invn;

            Samp A, B;
            prefetch_samp(t0, dx, dy, dz, p0x, p0y, p0z, h2, A);

            int it = 0;
#pragma unroll 2
            for (; it + 1 < cnt; it++) {
                const float tn = fmaf(tstep, (float)(it + 1), t0);
                if (it & 1) {
                    prefetch_samp(tn, dx, dy, dz, p0x, p0y, p0z, h2, A);
                    acc += consume_samp(B);
                } else {
                    prefetch_samp(tn, dx, dy, dz, p0x, p0y, p0z, h2, B);
                    acc += consume_samp(A);
                }
            }
            acc += (it & 1) ? consume_samp(B) : consume_samp(A);
        }
    }

    // pair reduction across the 2 sub-threads of this ray
    acc += __shfl_xor_sync(0xFFFFFFFFu, acc, 1);

    if (sub == 0) out[r] = acc * raylen / (float)n;
}

extern "C" void kernel_launch(void* const* d_in, const int* in_sizes, int n_in,
                              void* d_out, int out_size) {
    const float* src     = (const float*)d_in[0];
    const float* tgt     = (const float*)d_in[1];
    const float* density = (const float*)d_in[2];
    const float* spacing = (const float*)d_in[3];
    const float* origin  = (const float*)d_in[4];
    const int*   nptr    = (n_in > 5) ? (const int*)d_in[5] : nullptr;
    float* out = (float*)d_out;

    // 1) transpose volume into x-fastest fp16 scratch
    dim3 tb(32, 8);
    dim3 tg(DV / 32, DV / 64, DV);
    transpose_vol<<<tg, tb>>>(density);

    // 2) two threads per ray
    const int threads = 256;
    const int total   = out_size * 2;
    const int blocks  = (total + threads - 1) / threads;
    drr_kernel<<<blocks, threads>>>(src, tgt, spacing, origin, nptr, out, out_size);
}

// round 9
// speedup vs baseline: 1.4620x; 1.4620x over previous
#include <cuda_runtime.h>
#include <cuda_fp16.h>
#include <cstdint>

// DRR renderer: line integrals of trilinearly-interpolated 256^3 volume.
//
// R7 = R5 (best drr structure: flat-offset, PRMT pair-select, unroll-4,
// 32 regs) with the convert+trilerp replaced by fp16x2 SIMD lerps:
// y- and z-lerp run 2-wide in half2 (HFMA2), only the final x-lerp is fp32.
// ~10 fewer instructions/sample in an issue-bound kernel.

#define DV 256
#define DV2 (DV * DV)

__device__ __half g_volT[DV * DV * DV];  // 32 MB, x-fastest layout

__device__ __forceinline__ __half2 u32_as_half2(uint32_t x) {
    __half2 h;
    *reinterpret_cast<uint32_t*>(&h) = x;
    return h;
}

// -------- transpose: g_volT[k*DV2 + j*DV + i] = (half)vol[i*DV2 + j*DV + k] --------
__global__ void __launch_bounds__(256) transpose_vol(const float* __restrict__ v) {
    __shared__ float tile[32][65];            // [k_local][i_local(64)+pad]
    const int j  = blockIdx.z;
    const int i0 = blockIdx.y * 64;
    const int k0 = blockIdx.x * 32;
    const int tx = threadIdx.x, ty = threadIdx.y;

#pragma unroll
    for (int n = 0; n < 8; n++) {
        const int il = ty + n * 8;
        tile[tx][il] = v[(size_t)(i0 + il) * DV2 + j * DV + (k0 + tx)];
    }
    __syncthreads();
#pragma unroll
    for (int n = 0; n < 4; n++) {
        const int kl = ty + n * 8;
        const __half2 h = __floats2half2_rn(tile[kl][2 * tx], tile[kl][2 * tx + 1]);
        ((__half2*)g_volT)[(((size_t)(k0 + kl) * DV2 + j * DV + i0) >> 1) + tx] = h;
    }
}

// ----------------------------- main ray kernel ------------------------------
// 2 threads per ray: sub-thread handles samples s0+sub, s0+sub+2, ...
__global__ void __launch_bounds__(256) drr_kernel(
    const float* __restrict__ src,
    const float* __restrict__ tgt,
    const float* __restrict__ spacing,
    const float* __restrict__ origin,
    const int*   __restrict__ nptr,
    float* __restrict__ out,
    int n_rays)
{
    const int tid = blockIdx.x * blockDim.x + threadIdx.x;
    const int r   = tid >> 1;
    const int sub = tid & 1;
    if (r >= n_rays) return;

    const int n = nptr ? __ldg(nptr) : 128;

    const float ox = __ldg(origin + 0), oy = __ldg(origin + 1), oz = __ldg(origin + 2);
    const float hx = __ldg(spacing + 0), hy = __ldg(spacing + 1), hz = __ldg(spacing + 2);

    const float sxm = __ldg(src + 3 * r + 0);
    const float sym = __ldg(src + 3 * r + 1);
    const float szm = __ldg(src + 3 * r + 2);
    const float txm = __ldg(tgt + 3 * r + 0);
    const float tym = __ldg(tgt + 3 * r + 1);
    const float tzm = __ldg(tgt + 3 * r + 2);

    const float rx = txm - sxm, ry = tym - sym, rz = tzm - szm;
    const float raylen = sqrtf(fmaf(rx, rx, fmaf(ry, ry, rz * rz)));

    // voxel-space parametrization: idx(t) = p0 + t * d,  t = s/(n-1)
    const float p0x = (sxm - ox) / hx, p0y = (sym - oy) / hy, p0z = (szm - oz) / hz;
    const float dx = rx / hx, dy = ry / hy, dz = rz / hz;

    const float DM1 = (float)(DV - 1);

    // slab clip in t
    float tlo = 0.0f, thi = 1.0f;
    bool empty = false;
    {
        float p0[3] = {p0x, p0y, p0z};
        float dd[3] = {dx, dy, dz};
#pragma unroll
        for (int a = 0; a < 3; a++) {
            if (fabsf(dd[a]) > 1e-8f) {
                float inv = 1.0f / dd[a];
                float t1 = (0.0f - p0[a]) * inv;
                float t2 = (DM1 - p0[a]) * inv;
                tlo = fmaxf(tlo, fminf(t1, t2));
                thi = fminf(thi, fmaxf(t1, t2));
            } else if (p0[a] < 0.0f || p0[a] > DM1) {
                empty = true;
            }
        }
    }

    float acc = 0.0f;
    const float nm1 = (float)(n - 1);
    const float invn = (n > 1) ? 1.0f / nm1 : 0.0f;

    if (!empty && thi >= tlo) {
        // samples strictly within [tlo,thi] -> inside by construction
        const int s0 = max(0, (int)ceilf(fmaf(tlo, nm1, -1e-3f)));
        const int s1 = min(n - 1, (int)floorf(fmaf(thi, nm1, 1e-3f)));

        const uint32_t* __restrict__ h2 = (const uint32_t*)g_volT;
        const float CMAX = 254.99998f;   // floor <= 254, stays in-bounds

#pragma unroll 4
        for (int s = s0 + sub; s <= s1; s += 2) {
            const float t  = (float)s * invn;
            const float ix = fmaf(t, dx, p0x);
            const float iy = fmaf(t, dy, p0y);
            const float iz = fmaf(t, dz, p0z);

            const float cx = fminf(fmaxf(ix, 0.0f), CMAX);
            const float cy = fminf(fmaxf(iy, 0.0f), CMAX);
            const float cz = fminf(fmaxf(iz, 0.0f), CMAX);
            const int i0 = (int)cx, j0 = (int)cy, k0 = (int)cz;
            const float wx = cx - (float)i0;

            // 2-wide fp16 weights for y/z lerps
            const __half2 wy2 = __float2half2_rn(cy - (float)j0);
            const __half2 wz2 = __float2half2_rn(cz - (float)k0);

            // flat half2 element index of the aligned pair containing i0
            const int e = ((k0 << 16) + (j0 << 8) + i0) >> 1;
            const uint32_t sel = (i0 & 1) ? 0x5432u : 0x3210u;

            // rows: (j0,k0), (j0+1,k0), (j0,k0+1), (j0+1,k0+1)
            const uint32_t a0 = __ldg(h2 + e);
            const uint32_t b0 = __ldg(h2 + e + 1);
            const uint32_t a1 = __ldg(h2 + e + 128);
            const uint32_t b1 = __ldg(h2 + e + 129);
            const uint32_t a2 = __ldg(h2 + e + 32768);
            const uint32_t b2 = __ldg(h2 + e + 32769);
            const uint32_t a3 = __ldg(h2 + e + 32896);
            const uint32_t b3 = __ldg(h2 + e + 32897);

            // pairs (v_x0, v_x1) per row
            const __half2 p0h = u32_as_half2(__byte_perm(a0, b0, sel)); // j0,k0
            const __half2 p1h = u32_as_half2(__byte_perm(a1, b1, sel)); // j1,k0
            const __half2 p2h = u32_as_half2(__byte_perm(a2, b2, sel)); // j0,k1
            const __half2 p3h = u32_as_half2(__byte_perm(a3, b3, sel)); // j1,k1

            // y-lerp (2-wide), z-lerp (2-wide), then fp32 x-lerp
            const __half2 q0 = __hfma2(wy2, __hsub2(p1h, p0h), p0h);
            const __half2 q1 = __hfma2(wy2, __hsub2(p3h, p2h), p2h);
            const __half2 u  = __hfma2(wz2, __hsub2(q1, q0), q0);

            const float A = __low2float(u);
            const float Bv = __high2float(u);
            acc += fmaf(wx, Bv - A, A);
        }
    }

    // pair reduction across the 2 sub-threads of this ray
    acc += __shfl_xor_sync(0xFFFFFFFFu, acc, 1);

    if (sub == 0) out[r] = acc * raylen / (float)n;
}

extern "C" void kernel_launch(void* const* d_in, const int* in_sizes, int n_in,
                              void* d_out, int out_size) {
    const float* src     = (const float*)d_in[0];
    const float* tgt     = (const float*)d_in[1];
    const float* density = (const float*)d_in[2];
    const float* spacing = (const float*)d_in[3];
    const float* origin  = (const float*)d_in[4];
    const int*   nptr    = (n_in > 5) ? (const int*)d_in[5] : nullptr;
    float* out = (float*)d_out;

    // 1) transpose volume into x-fastest fp16 scratch
    dim3 tb(32, 8);
    dim3 tg(DV / 32, DV / 64, DV);
    transpose_vol<<<tg, tb>>>(density);

    // 2) two threads per ray
    const int threads = 256;
    const int total   = out_size * 2;
    const int blocks  = (total + threads - 1) / threads;
    drr_kernel<<<blocks, threads>>>(src, tgt, spacing, origin, nptr, out, out_size);
}